// round 8
// baseline (speedup 1.0000x reference)
#include <cuda_runtime.h>
#include <cstdint>
#include <cstddef>

// Problem constants
#define NU      100
#define TSTEPS  60
#define BTOT    8192
// output offsets (all float32, concatenated in reference tuple order)
static const size_t OFFU  = 0;         // u:        (B,60,7)
static const size_t OFFT  = 3440640;   // target:   (B,60)
static const size_t OFFRS = 3932160;   // respmask: (B,60)
static const size_t OFFL  = 4423680;   // licked:   (B,)
static const size_t OFFR  = 4431872;   // reward:   (B,)
static const size_t OFFZ  = 4440064;   // z_seq:    (B,60)
static const size_t OFFYF = 4931584;   // yf:       (B,100)

// noise_scale = 0.15 * sqrt(2*0.2)
#define NSCALE 0.09486832980505138f

// 8 trials/warp, 8 warps (256 thr)/block = 64 trials/block, grid 128.
#define TPW 8

typedef unsigned long long ull;

// ---- packed f32x2 helpers (Blackwell FFMA2) ----
__device__ __forceinline__ ull pack2(float lo, float hi){
    ull r;
    asm("mov.b64 %0, {%1, %2};" : "=l"(r) : "f"(lo), "f"(hi));
    return r;
}
__device__ __forceinline__ void fma2(ull &a, ull x, ull y){
    asm("fma.rn.f32x2 %0, %1, %2, %0;" : "+l"(a) : "l"(x), "l"(y));
}
__device__ __forceinline__ float2 unpk(ull v){
    float lo, hi;
    asm("mov.b64 {%0, %1}, %2;" : "=f"(lo), "=f"(hi) : "l"(v));
    return make_float2(lo, hi);
}

// Shared layout (floats):
//   Wpk [100][128] : Wpk[j*128 + 4*l + u] = Wrec[(32u+l)][j]  (0 if unit>=100)
//                    -> per lane, (w_u0,w_u1,w_u2,w_u3) contiguous = 2 f32x2 pairs
//   Ysh [100][132] : per warp 16 floats: trial values DUPLICATED [y0,y0,y1,y1,...]
//   WinS[7][128]   : WinS[k*128 + i] = |W_in_raw[i][k]|  (0 pad)
#define YS 132
#define SM_W   0
#define SM_Y   12800
#define SM_WIN (12800 + 100*YS)
#define SM_FLOATS (12800 + 100*YS + 7*128)

__global__ __launch_bounds__(256, 1)
void rnn_dynrouting_kernel(
    const float* __restrict__ y0,      const float* __restrict__ noise,
    const int*   __restrict__ stimI,   const int*   __restrict__ rewI,
    const int*   __restrict__ instrI,
    const float* __restrict__ WinRaw,  const float* __restrict__ Wrec,
    const float* __restrict__ brec,    const float* __restrict__ wout,
    const float* __restrict__ bout,
    float* __restrict__ out)
{
    extern __shared__ float sm[];
    float* Wpk  = sm + SM_W;
    float* Ysh  = sm + SM_Y;
    float* WinS = sm + SM_WIN;

    const int tid = threadIdx.x;

    // ---- one-time shared init ----
    for (int idx = tid; idx < 100*128; idx += 256) {
        int j = idx >> 7, c = idx & 127;
        int l = c >> 2, u = c & 3;            // packed lane-major: c = 4l+u
        int i = 32*u + l;                     // unit id (interleaved ownership)
        Wpk[idx] = (i < NU) ? Wrec[i*NU + j] : 0.0f;
    }
    for (int idx = tid; idx < 7*128; idx += 256) {
        int k = idx >> 7, i = idx & 127;
        WinS[idx] = (i < NU) ? fabsf(WinRaw[i*7 + k]) : 0.0f;
    }
    __syncthreads();

    const int lane = tid & 31;
    const int warp = tid >> 5;
    const int tb   = blockIdx.x * 64 + warp * TPW;   // first trial of this warp
    // interleaved unit ownership: unit(u) = 32u + lane
    const bool v3  = (lane < 4);                     // u==3 validity

    // per-lane constants (4 units)
    float w4[4], w5[4], w6[4], wo[4];
    #pragma unroll
    for (int u = 0; u < 4; u++) {
        int i = 32*u + lane;
        bool v = (u < 3) || v3;
        w4[u] = WinS[4*128 + i];
        w5[u] = WinS[5*128 + i];
        w6[u] = WinS[6*128 + i];
        wo[u] = v ? wout[i] : 0.0f;
    }
    // bias packed per unit-pair: (b_u0,b_u1), (b_u2,b_u3)
    ull bdp[2];
    {
        float bf[4];
        #pragma unroll
        for (int u = 0; u < 4; u++) {
            bool v = (u < 3) || v3;
            bf[u] = v ? brec[32*u + lane] : 0.0f;
        }
        bdp[0] = pack2(bf[0], bf[1]);
        bdp[1] = pack2(bf[2], bf[3]);
    }
    const float b0 = bout[0];

    // per-trial constants, replicated in every lane (bit-packed)
    unsigned isRewM = 0, instrBM = 0, stimP = 0;
    #pragma unroll
    for (int s = 0; s < TPW; s++) {
        int b = tb + s;
        int sv = stimI[b];
        stimP  |= (unsigned)(sv & 3) << (2*s);
        isRewM |= (unsigned)(sv == rewI[b]) << s;
        instrBM|= (unsigned)(instrI[b] > 0) << s;
    }

    // per-trial state (replicated)
    unsigned lickedM = 0, instrFiredM = 0;
    int lickT[TPW];
    #pragma unroll
    for (int s = 0; s < TPW; s++) lickT[s] = TSTEPS + 1;

    // y state: y[u][s]
    float y[4][TPW];
    #pragma unroll
    for (int u = 0; u < 4; u++) {
        bool v = (u < 3) || v3;
        #pragma unroll
        for (int s = 0; s < TPW; s++)
            y[u][s] = v ? y0[(size_t)(tb + s)*NU + 32*u + lane] : 0.0f;
    }
    // publish initial y, DUPLICATED per trial (conflict-free: stride 132 = 4 mod 32)
    #pragma unroll
    for (int u = 0; u < 4; u++) {
        if (u < 3 || v3) {
            float* row = Ysh + (size_t)(32*u + lane)*YS + 16*warp;
            *reinterpret_cast<float4*>(row)      = make_float4(y[u][0], y[u][0], y[u][1], y[u][1]);
            *reinterpret_cast<float4*>(row + 4)  = make_float4(y[u][2], y[u][2], y[u][3], y[u][3]);
            *reinterpret_cast<float4*>(row + 8)  = make_float4(y[u][4], y[u][4], y[u][5], y[u][5]);
            *reinterpret_cast<float4*>(row + 12) = make_float4(y[u][6], y[u][6], y[u][7], y[u][7]);
        }
    }
    __syncwarp();

    const float* wp = Wpk + 4*lane;
    const float* yp = Ysh + 16*warp;

    // single noise base pointer; per-trial/unit offsets become LDG immediates
    const float* nb = noise + (size_t)tb*(TSTEPS*NU) + lane;

    float nz[4][TPW];

    // ==================== time loop ====================
    for (int t = 0; t < TSTEPS; t++) {
        const bool inResp = (t >= 20) && (t < 35);
        const bool inStim = (t >= 10) && (t < 15);

        // ---- per-trial coefficients (replicated in all lanes) ----
        float cA[TPW], cB[TPW];
        unsigned instrActM = 0;
        #pragma unroll
        for (int s = 0; s < TPW; s++) {
            bool lic = (lickedM >> s) & 1;
            bool ifd = (instrFiredM >> s) & 1;
            bool irw = (isRewM >> s) & 1;
            bool ib  = (instrBM >> s) & 1;
            bool delivered = ifd || (lic && irw);
            if (ib && !delivered && (t == 30)) instrFiredM |= 1u << s;
            bool instrAct = ((instrFiredM >> s) & 1) && (t >= 30) && (t < 35);
            if (instrAct) instrActM |= 1u << s;
            bool lickDyn = lic && (t > lickT[s]) && (t < lickT[s] + 5);
            cA[s] = (instrAct ? 1.0f : 0.0f) + ((lickDyn && irw) ? 1.0f : 0.0f);
            cB[s] = lickDyn ? 1.0f : 0.0f;
        }

        // ---- prefetch noise (coalesced, immediate offsets; hidden under matvec) ----
        #pragma unroll
        for (int s = 0; s < TPW; s++) {
            const float* p = nb + (size_t)s*(TSTEPS*NU);
            nz[0][s] = __ldg(p);
            nz[1][s] = __ldg(p + 32);
            nz[2][s] = __ldg(p + 64);
            nz[3][s] = v3 ? __ldg(p + 96) : 0.0f;
        }
        nb += NU;

        // ---- matvec: acc[p][s], p = unit-pair, s = trial (MOV-free inner loop) ----
        ull acc[2][TPW];
        #pragma unroll
        for (int s = 0; s < TPW; s++) { acc[0][s] = bdp[0]; acc[1][s] = bdp[1]; }
        #pragma unroll 10
        for (int j = 0; j < NU; j++) {
            ulonglong2 w2 = *reinterpret_cast<const ulonglong2*>(wp + j*128); // (wu0,wu1),(wu2,wu3)
            const float* yj = yp + j*YS;
            ulonglong2 ya = *reinterpret_cast<const ulonglong2*>(yj);      // trials 0,1 (dup)
            ulonglong2 yb = *reinterpret_cast<const ulonglong2*>(yj + 4);  // trials 2,3
            ulonglong2 yc = *reinterpret_cast<const ulonglong2*>(yj + 8);  // trials 4,5
            ulonglong2 yd = *reinterpret_cast<const ulonglong2*>(yj + 12); // trials 6,7
            fma2(acc[0][0], w2.x, ya.x); fma2(acc[0][1], w2.x, ya.y);
            fma2(acc[0][2], w2.x, yb.x); fma2(acc[0][3], w2.x, yb.y);
            fma2(acc[0][4], w2.x, yc.x); fma2(acc[0][5], w2.x, yc.y);
            fma2(acc[0][6], w2.x, yd.x); fma2(acc[0][7], w2.x, yd.y);
            fma2(acc[1][0], w2.y, ya.x); fma2(acc[1][1], w2.y, ya.y);
            fma2(acc[1][2], w2.y, yb.x); fma2(acc[1][3], w2.y, yb.y);
            fma2(acc[1][4], w2.y, yc.x); fma2(acc[1][5], w2.y, yc.y);
            fma2(acc[1][6], w2.y, yd.x); fma2(acc[1][7], w2.y, yd.y);
        }

        // ---- epilogue (fused unpack): pre -> relu -> leaky update ----
        const float a6 = inResp ? 1.0f : 0.0f;
        const bool doAdd = (t >= 20);   // cA/cB only nonzero from t>=21/30
        #pragma unroll
        for (int p = 0; p < 2; p++) {
            #pragma unroll
            for (int s = 0; s < TPW; s++) {
                float2 v = unpk(acc[p][s]);
                int u0 = 2*p, u1 = 2*p + 1;
                float pa = v.x, pb = v.y;
                if (inStim) {
                    int sv = (stimP >> (2*s)) & 3;
                    pa += WinS[sv*128 + 32*u0 + lane];
                    pb += WinS[sv*128 + 32*u1 + lane];
                }
                pa = fmaf(a6, w6[u0], pa);
                pb = fmaf(a6, w6[u1], pb);
                if (doAdd) {
                    pa = fmaf(cA[s], w4[u0], fmaf(cB[s], w5[u0], pa));
                    pb = fmaf(cA[s], w4[u1], fmaf(cB[s], w5[u1], pb));
                }
                pa = fmaf(NSCALE, nz[u0][s], pa);
                pb = fmaf(NSCALE, nz[u1][s], pb);
                y[u0][s] = 0.8f * y[u0][s] + 0.2f * fmaxf(pa, 0.0f);
                y[u1][s] = 0.8f * y[u1][s] + 0.2f * fmaxf(pb, 0.0f);
            }
        }

        // ---- publish y, duplicated (conflict-free) ----
        __syncwarp();   // all lanes finished reading Ysh this step
        #pragma unroll
        for (int u = 0; u < 4; u++) {
            if (u < 3 || v3) {
                float* row = Ysh + (size_t)(32*u + lane)*YS + 16*warp;
                *reinterpret_cast<float4*>(row)      = make_float4(y[u][0], y[u][0], y[u][1], y[u][1]);
                *reinterpret_cast<float4*>(row + 4)  = make_float4(y[u][2], y[u][2], y[u][3], y[u][3]);
                *reinterpret_cast<float4*>(row + 8)  = make_float4(y[u][4], y[u][4], y[u][5], y[u][5]);
                *reinterpret_cast<float4*>(row + 12) = make_float4(y[u][6], y[u][6], y[u][7], y[u][7]);
            }
        }

        // ---- readout: logit[s] = y . w_out + b0 via shuffle butterfly ----
        float part[TPW];
        #pragma unroll
        for (int s = 0; s < TPW; s++) {
            part[s] = fmaf(y[0][s], wo[0],
                      fmaf(y[1][s], wo[1],
                      fmaf(y[2][s], wo[2], y[3][s] * wo[3])));
        }
        #pragma unroll
        for (int off = 16; off > 0; off >>= 1) {
            #pragma unroll
            for (int s = 0; s < TPW; s++)
                part[s] += __shfl_xor_sync(0xffffffffu, part[s], off);
        }

        // ---- lick state machine + per-step outputs ----
        unsigned u5M = 0, u4M = 0;
        #pragma unroll
        for (int s = 0; s < TPW; s++) {
            float lg = part[s] + b0;
            bool lic = (lickedM >> s) & 1;
            bool trig = inResp && !lic && (lg > 0.0f);   // sigmoid(x)>0.5 <=> x>0
            if (trig) { lickT[s] = t; lickedM |= 1u << s; }
            bool lic2 = (lickedM >> s) & 1;
            bool u5 = lic2 && (t >= lickT[s]) && (t < lickT[s] + 5);
            bool u4 = ((instrActM >> s) & 1) || (u5 && ((isRewM >> s) & 1));
            if (u5) u5M |= 1u << s;
            if (u4) u4M |= 1u << s;
        }
        // lane s (<8) writes trial s's z, u[...,4], u[...,5]
        float myPart = part[0];
        #pragma unroll
        for (int s = 1; s < TPW; s++) if ((lane & 7) == s) myPart = part[s];
        if (lane < TPW) {
            int s = lane;
            float lg = myPart + b0;
            out[OFFZ + (size_t)(tb + s)*TSTEPS + t] = 1.0f / (1.0f + __expf(-lg));
            size_t ub = OFFU + (size_t)(tb + s)*(TSTEPS*7) + (size_t)t*7;
            out[ub + 4] = ((u4M >> s) & 1) ? 1.0f : 0.0f;
            out[ub + 5] = ((u5M >> s) & 1) ? 1.0f : 0.0f;
        }
        __syncwarp();   // publish visible before next step's matvec reads
    }

    // ==================== final outputs ====================
    // yf (coalesced scalar stores)
    #pragma unroll
    for (int u = 0; u < 4; u++) {
        if (u < 3 || v3) {
            #pragma unroll
            for (int s = 0; s < TPW; s++)
                out[OFFYF + (size_t)(tb + s)*NU + 32*u + lane] = y[u][s];
        }
    }
    // licked / reward_delivered
    if (lane < TPW) {
        int s = lane;
        bool lic = (lickedM >> s) & 1;
        bool irw = (isRewM >> s) & 1;
        bool ifd = (instrFiredM >> s) & 1;
        out[OFFL + (size_t)(tb + s)] = lic ? 1.0f : 0.0f;
        out[OFFR + (size_t)(tb + s)] = (ifd || (lic && irw)) ? 1.0f : 0.0f;
    }
    // static per-(trial,t) outputs
    for (int idx = lane; idx < TPW*TSTEPS; idx += 32) {
        int s = idx / TSTEPS;
        int t = idx - s*TSTEPS;
        size_t b = (size_t)(tb + s);
        bool resp = (t >= 20) && (t < 35);
        bool stm  = (t >= 10) && (t < 15);
        int sv = (stimP >> (2*s)) & 3;
        bool irw = (isRewM >> s) & 1;
        float* ub = out + OFFU + b*(TSTEPS*7) + (size_t)t*7;
        ub[0] = (stm && sv == 0) ? 1.0f : 0.0f;
        ub[1] = (stm && sv == 1) ? 1.0f : 0.0f;
        ub[2] = (stm && sv == 2) ? 1.0f : 0.0f;
        ub[3] = (stm && sv == 3) ? 1.0f : 0.0f;
        ub[6] = resp ? 1.0f : 0.0f;
        out[OFFT  + b*TSTEPS + t] = (irw && resp) ? 1.0f : 0.0f;
        out[OFFRS + b*TSTEPS + t] = resp ? 1.0f : 0.0f;
    }
}

extern "C" void kernel_launch(void* const* d_in, const int* in_sizes, int n_in,
                              void* d_out, int out_size) {
    const float* y0     = (const float*)d_in[0];
    const float* noise  = (const float*)d_in[1];
    const int*   stim   = (const int*)  d_in[2];
    const int*   rew    = (const int*)  d_in[3];
    const int*   instr  = (const int*)  d_in[4];
    const float* WinRaw = (const float*)d_in[5];
    const float* Wrec   = (const float*)d_in[6];
    const float* brec   = (const float*)d_in[7];
    const float* wout   = (const float*)d_in[8];
    const float* bout   = (const float*)d_in[9];
    float* out = (float*)d_out;

    const int smem_bytes = SM_FLOATS * (int)sizeof(float);  // ~107.6 KB
    cudaFuncSetAttribute(rnn_dynrouting_kernel,
                         cudaFuncAttributeMaxDynamicSharedMemorySize, smem_bytes);
    rnn_dynrouting_kernel<<<BTOT/64, 256, smem_bytes>>>(
        y0, noise, stim, rew, instr, WinRaw, Wrec, brec, wout, bout, out);
}

// round 9
// speedup vs baseline: 1.3180x; 1.3180x over previous
#include <cuda_runtime.h>
#include <cstdint>
#include <cstddef>

// Problem constants
#define NU      100
#define TSTEPS  60
#define BTOT    8192
// output offsets (all float32, concatenated in reference tuple order)
static const size_t OFFU  = 0;         // u:        (B,60,7)
static const size_t OFFT  = 3440640;   // target:   (B,60)
static const size_t OFFRS = 3932160;   // respmask: (B,60)
static const size_t OFFL  = 4423680;   // licked:   (B,)
static const size_t OFFR  = 4431872;   // reward:   (B,)
static const size_t OFFZ  = 4440064;   // z_seq:    (B,60)
static const size_t OFFYF = 4931584;   // yf:       (B,100)

// noise_scale = 0.15 * sqrt(2*0.2)
#define NSCALE 0.09486832980505138f

// 8 trials/warp, 8 warps (256 thr)/block = 64 trials/block, grid 128.
#define TPW 8

typedef unsigned long long ull;

// ---- packed f32x2 helpers (Blackwell FFMA2) ----
__device__ __forceinline__ ull dup2(float x){
    ull r;
    asm("mov.b64 %0, {%1, %1};" : "=l"(r) : "f"(x));
    return r;
}
__device__ __forceinline__ void fma2(ull &a, ull x, ull y){
    asm("fma.rn.f32x2 %0, %1, %2, %0;" : "+l"(a) : "l"(x), "l"(y));
}
__device__ __forceinline__ float2 unpk(ull v){
    float lo, hi;
    asm("mov.b64 {%0, %1}, %2;" : "=f"(lo), "=f"(hi) : "l"(v));
    return make_float2(lo, hi);
}

// Shared layout (floats):
//   Wpk [100][128] : Wpk[j*128 + 4l + u] = Wrec[(32u+l)][j] for u<3,
//                    slot u=3 holds the TAIL unit's weight: Wrec[96+(l>>3)][j].
//   Ysh [100][68]  : Ysh[j*68 + 8*warp + s]  (warp-private trial columns)
//   WinS[7][128]   : WinS[k*128 + i] = |W_in_raw[i][k]|  (0 pad)
#define YS 68
#define SM_W   0
#define SM_Y   12800
#define SM_WIN (12800 + 100*YS)
#define SM_FLOATS (12800 + 100*YS + 7*128)

__global__ __launch_bounds__(256, 1)
void rnn_dynrouting_kernel(
    const float* __restrict__ y0,      const float* __restrict__ noise,
    const int*   __restrict__ stimI,   const int*   __restrict__ rewI,
    const int*   __restrict__ instrI,
    const float* __restrict__ WinRaw,  const float* __restrict__ Wrec,
    const float* __restrict__ brec,    const float* __restrict__ wout,
    const float* __restrict__ bout,
    float* __restrict__ out)
{
    extern __shared__ float sm[];
    float* Wpk  = sm + SM_W;
    float* Ysh  = sm + SM_Y;
    float* WinS = sm + SM_WIN;

    const int tid = threadIdx.x;

    // ---- one-time shared init ----
    for (int idx = tid; idx < 100*128; idx += 256) {
        int j = idx >> 7, c = idx & 127;
        int l = c >> 2, u = c & 3;
        int i = (u < 3) ? (32*u + l) : (96 + (l >> 3));   // tail unit in slot 3
        Wpk[idx] = Wrec[i*NU + j];
    }
    for (int idx = tid; idx < 7*128; idx += 256) {
        int k = idx >> 7, i = idx & 127;
        WinS[idx] = (i < NU) ? fabsf(WinRaw[i*7 + k]) : 0.0f;
    }
    __syncthreads();

    const int lane = tid & 31;
    const int warp = tid >> 5;
    const int tb   = blockIdx.x * 64 + warp * TPW;   // first trial of this warp
    // main units: 32u + lane (u=0..2); tail: unit ut for trial st
    const int ut = 96 + (lane >> 3);
    const int st = lane & 7;

    // per-lane constants
    float w4[3], w5[3], w6[3], wo[3];
    ull bd[3];
    #pragma unroll
    for (int u = 0; u < 3; u++) {
        int i = 32*u + lane;
        w4[u] = WinS[4*128 + i];
        w5[u] = WinS[5*128 + i];
        w6[u] = WinS[6*128 + i];
        wo[u] = wout[i];
        bd[u] = dup2(brec[i]);
    }
    const float w4t = WinS[4*128 + ut];
    const float w5t = WinS[5*128 + ut];
    const float w6t = WinS[6*128 + ut];
    const float wot = wout[ut];
    const float bT  = brec[ut];
    const float b0  = bout[0];

    // per-trial constants, replicated in every lane (bit-packed)
    unsigned isRewM = 0, instrBM = 0, stimP = 0;
    #pragma unroll
    for (int s = 0; s < TPW; s++) {
        int b = tb + s;
        int sv = stimI[b];
        stimP  |= (unsigned)(sv & 3) << (2*s);
        isRewM |= (unsigned)(sv == rewI[b]) << s;
        instrBM|= (unsigned)(instrI[b] > 0) << s;
    }

    // per-trial state (replicated)
    unsigned lickedM = 0, instrFiredM = 0;
    int lickT[TPW];
    #pragma unroll
    for (int s = 0; s < TPW; s++) lickT[s] = TSTEPS + 1;

    // y state
    float y[3][TPW];
    #pragma unroll
    for (int u = 0; u < 3; u++)
        #pragma unroll
        for (int s = 0; s < TPW; s++)
            y[u][s] = y0[(size_t)(tb + s)*NU + 32*u + lane];
    float yt = y0[(size_t)(tb + st)*NU + ut];

    // publish initial y (main rows conflict-free; tail rows 96-99 covered exactly)
    #pragma unroll
    for (int u = 0; u < 3; u++) {
        float* row = Ysh + (size_t)(32*u + lane)*YS + TPW*warp;
        *reinterpret_cast<float4*>(row)     = make_float4(y[u][0], y[u][1], y[u][2], y[u][3]);
        *reinterpret_cast<float4*>(row + 4) = make_float4(y[u][4], y[u][5], y[u][6], y[u][7]);
    }
    Ysh[(size_t)ut*YS + TPW*warp + st] = yt;
    __syncwarp();

    const float* wp  = Wpk + 4*lane;
    const float* yp  = Ysh + TPW*warp;            // broadcast base for trial pairs
    const float* ypt = Ysh + TPW*warp + st;       // per-lane tail-y base

    // noise pointers
    const float* nb  = noise + (size_t)tb*(TSTEPS*NU) + lane;
    const float* nbt = noise + (size_t)(tb + st)*(TSTEPS*NU) + ut;

    float nz[3][TPW];
    float nzT;

    // ==================== time loop ====================
    for (int t = 0; t < TSTEPS; t++) {
        const bool inResp = (t >= 20) && (t < 35);
        const bool inStim = (t >= 10) && (t < 15);

        // ---- per-trial coefficients (replicated; lickDynM mask kept for tail) ----
        float cA[TPW], cB[TPW];
        unsigned instrActM = 0, lickDynM = 0;
        #pragma unroll
        for (int s = 0; s < TPW; s++) {
            bool lic = (lickedM >> s) & 1;
            bool ifd = (instrFiredM >> s) & 1;
            bool irw = (isRewM >> s) & 1;
            bool ib  = (instrBM >> s) & 1;
            bool delivered = ifd || (lic && irw);
            if (ib && !delivered && (t == 30)) instrFiredM |= 1u << s;
            bool instrAct = ((instrFiredM >> s) & 1) && (t >= 30) && (t < 35);
            if (instrAct) instrActM |= 1u << s;
            bool lickDyn = lic && (t > lickT[s]) && (t < lickT[s] + 5);
            if (lickDyn) lickDynM |= 1u << s;
            cA[s] = (instrAct ? 1.0f : 0.0f) + ((lickDyn && irw) ? 1.0f : 0.0f);
            cB[s] = lickDyn ? 1.0f : 0.0f;
        }

        // ---- prefetch noise (hidden under matvec) ----
        #pragma unroll
        for (int s = 0; s < TPW; s++) {
            const float* p = nb + (size_t)s*(TSTEPS*NU);
            nz[0][s] = __ldg(p);
            nz[1][s] = __ldg(p + 32);
            nz[2][s] = __ldg(p + 64);
        }
        nzT = __ldg(nbt);
        nb += NU; nbt += NU;

        // ---- matvec: 3 f32x2 unit-slices + scalar tail ----
        ull acc[3][4];
        #pragma unroll
        for (int u = 0; u < 3; u++) {
            acc[u][0] = bd[u]; acc[u][1] = bd[u]; acc[u][2] = bd[u]; acc[u][3] = bd[u];
        }
        float accT = bT;
        #pragma unroll 10
        for (int j = 0; j < NU; j++) {
            float4 w = *reinterpret_cast<const float4*>(wp + j*128);  // w_u0,w_u1,w_u2,w_tail
            ulonglong2 ya = *reinterpret_cast<const ulonglong2*>(yp + j*YS);     // trials 0-3
            ulonglong2 yb = *reinterpret_cast<const ulonglong2*>(yp + j*YS + 4); // trials 4-7
            float yTj = ypt[j*YS];                                    // tail-y (trial st)
            ull w0 = dup2(w.x), w1 = dup2(w.y), w2 = dup2(w.z);
            fma2(acc[0][0], w0, ya.x); fma2(acc[0][1], w0, ya.y); fma2(acc[0][2], w0, yb.x); fma2(acc[0][3], w0, yb.y);
            fma2(acc[1][0], w1, ya.x); fma2(acc[1][1], w1, ya.y); fma2(acc[1][2], w1, yb.x); fma2(acc[1][3], w1, yb.y);
            fma2(acc[2][0], w2, ya.x); fma2(acc[2][1], w2, ya.y); fma2(acc[2][2], w2, yb.x); fma2(acc[2][3], w2, yb.y);
            accT = fmaf(w.w, yTj, accT);
        }

        // ---- epilogue: main slices ----
        const float a6 = inResp ? 1.0f : 0.0f;
        const bool doAdd = (t >= 20);   // cA/cB only nonzero from t>=21/30
        #pragma unroll
        for (int u = 0; u < 3; u++) {
            #pragma unroll
            for (int p = 0; p < 4; p++) {
                float2 v = unpk(acc[u][p]);
                int s0 = 2*p, s1 = 2*p + 1;
                float pa = v.x, pb = v.y;
                if (inStim) {
                    pa += WinS[((stimP >> (2*s0)) & 3)*128 + 32*u + lane];
                    pb += WinS[((stimP >> (2*s1)) & 3)*128 + 32*u + lane];
                }
                pa = fmaf(a6, w6[u], pa);
                pb = fmaf(a6, w6[u], pb);
                if (doAdd) {
                    pa = fmaf(cA[s0], w4[u], fmaf(cB[s0], w5[u], pa));
                    pb = fmaf(cA[s1], w4[u], fmaf(cB[s1], w5[u], pb));
                }
                pa = fmaf(NSCALE, nz[u][s0], pa);
                pb = fmaf(NSCALE, nz[u][s1], pb);
                y[u][s0] = 0.8f * y[u][s0] + 0.2f * fmaxf(pa, 0.0f);
                y[u][s1] = 0.8f * y[u][s1] + 0.2f * fmaxf(pb, 0.0f);
            }
        }
        // ---- epilogue: tail (unit ut, trial st) ----
        {
            float p = accT;
            if (inStim) p += WinS[((stimP >> (2*st)) & 3)*128 + ut];
            p = fmaf(a6, w6t, p);
            if (doAdd) {
                float cAt = (float)((instrActM >> st) & 1) + (float)(((lickDynM & isRewM) >> st) & 1);
                float cBt = (float)((lickDynM >> st) & 1);
                p = fmaf(cAt, w4t, fmaf(cBt, w5t, p));
            }
            p = fmaf(NSCALE, nzT, p);
            yt = 0.8f * yt + 0.2f * fmaxf(p, 0.0f);
        }

        // ---- publish y ----
        __syncwarp();   // all lanes finished reading Ysh this step
        #pragma unroll
        for (int u = 0; u < 3; u++) {
            float* row = Ysh + (size_t)(32*u + lane)*YS + TPW*warp;
            *reinterpret_cast<float4*>(row)     = make_float4(y[u][0], y[u][1], y[u][2], y[u][3]);
            *reinterpret_cast<float4*>(row + 4) = make_float4(y[u][4], y[u][5], y[u][6], y[u][7]);
        }
        Ysh[(size_t)ut*YS + TPW*warp + st] = yt;

        // ---- readout: main partials + butterfly; tail via class-reduce + broadcast ----
        float part[TPW];
        #pragma unroll
        for (int s = 0; s < TPW; s++)
            part[s] = fmaf(y[0][s], wo[0], fmaf(y[1][s], wo[1], y[2][s] * wo[2]));
        #pragma unroll
        for (int off = 16; off > 0; off >>= 1) {
            #pragma unroll
            for (int s = 0; s < TPW; s++)
                part[s] += __shfl_xor_sync(0xffffffffu, part[s], off);
        }
        float tr = wot * yt;                       // tail contribution, trial st
        tr += __shfl_xor_sync(0xffffffffu, tr, 8);
        tr += __shfl_xor_sync(0xffffffffu, tr, 16); // lanes of class s hold trial-s tail sum
        float lg[TPW];
        #pragma unroll
        for (int s = 0; s < TPW; s++)
            lg[s] = part[s] + __shfl_sync(0xffffffffu, tr, s) + b0;

        // ---- lick state machine + per-step outputs ----
        unsigned u5M = 0, u4M = 0;
        #pragma unroll
        for (int s = 0; s < TPW; s++) {
            bool lic = (lickedM >> s) & 1;
            bool trig = inResp && !lic && (lg[s] > 0.0f);   // sigmoid(x)>0.5 <=> x>0
            if (trig) { lickT[s] = t; lickedM |= 1u << s; }
            bool lic2 = (lickedM >> s) & 1;
            bool u5 = lic2 && (t >= lickT[s]) && (t < lickT[s] + 5);
            bool u4 = ((instrActM >> s) & 1) || (u5 && ((isRewM >> s) & 1));
            if (u5) u5M |= 1u << s;
            if (u4) u4M |= 1u << s;
        }
        float myLg = lg[0];
        #pragma unroll
        for (int s = 1; s < TPW; s++) if ((lane & 7) == s) myLg = lg[s];
        if (lane < TPW) {
            int s = lane;
            out[OFFZ + (size_t)(tb + s)*TSTEPS + t] = 1.0f / (1.0f + __expf(-myLg));
            size_t ub = OFFU + (size_t)(tb + s)*(TSTEPS*7) + (size_t)t*7;
            out[ub + 4] = ((u4M >> s) & 1) ? 1.0f : 0.0f;
            out[ub + 5] = ((u5M >> s) & 1) ? 1.0f : 0.0f;
        }
        __syncwarp();   // publish visible before next step's matvec reads
    }

    // ==================== final outputs ====================
    // yf
    #pragma unroll
    for (int u = 0; u < 3; u++) {
        #pragma unroll
        for (int s = 0; s < TPW; s++)
            out[OFFYF + (size_t)(tb + s)*NU + 32*u + lane] = y[u][s];
    }
    out[OFFYF + (size_t)(tb + st)*NU + ut] = yt;
    // licked / reward_delivered
    if (lane < TPW) {
        int s = lane;
        bool lic = (lickedM >> s) & 1;
        bool irw = (isRewM >> s) & 1;
        bool ifd = (instrFiredM >> s) & 1;
        out[OFFL + (size_t)(tb + s)] = lic ? 1.0f : 0.0f;
        out[OFFR + (size_t)(tb + s)] = (ifd || (lic && irw)) ? 1.0f : 0.0f;
    }
    // static per-(trial,t) outputs
    for (int idx = lane; idx < TPW*TSTEPS; idx += 32) {
        int s = idx / TSTEPS;
        int t = idx - s*TSTEPS;
        size_t b = (size_t)(tb + s);
        bool resp = (t >= 20) && (t < 35);
        bool stm  = (t >= 10) && (t < 15);
        int sv = (stimP >> (2*s)) & 3;
        bool irw = (isRewM >> s) & 1;
        float* ub = out + OFFU + b*(TSTEPS*7) + (size_t)t*7;
        ub[0] = (stm && sv == 0) ? 1.0f : 0.0f;
        ub[1] = (stm && sv == 1) ? 1.0f : 0.0f;
        ub[2] = (stm && sv == 2) ? 1.0f : 0.0f;
        ub[3] = (stm && sv == 3) ? 1.0f : 0.0f;
        ub[6] = resp ? 1.0f : 0.0f;
        out[OFFT  + b*TSTEPS + t] = (irw && resp) ? 1.0f : 0.0f;
        out[OFFRS + b*TSTEPS + t] = resp ? 1.0f : 0.0f;
    }
}

extern "C" void kernel_launch(void* const* d_in, const int* in_sizes, int n_in,
                              void* d_out, int out_size) {
    const float* y0     = (const float*)d_in[0];
    const float* noise  = (const float*)d_in[1];
    const int*   stim   = (const int*)  d_in[2];
    const int*   rew    = (const int*)  d_in[3];
    const int*   instr  = (const int*)  d_in[4];
    const float* WinRaw = (const float*)d_in[5];
    const float* Wrec   = (const float*)d_in[6];
    const float* brec   = (const float*)d_in[7];
    const float* wout   = (const float*)d_in[8];
    const float* bout   = (const float*)d_in[9];
    float* out = (float*)d_out;

    const int smem_bytes = SM_FLOATS * (int)sizeof(float);  // ~82 KB
    cudaFuncSetAttribute(rnn_dynrouting_kernel,
                         cudaFuncAttributeMaxDynamicSharedMemorySize, smem_bytes);
    rnn_dynrouting_kernel<<<BTOT/64, 256, smem_bytes>>>(
        y0, noise, stim, rew, instr, WinRaw, Wrec, brec, wout, bout, out);
}